// round 14
// baseline (speedup 1.0000x reference)
#include <cuda_runtime.h>
#include <math.h>

#define H      64
#define NFINE  (1 << 20)          // fine grid intervals over [0,1]
#define NC     (1 << 11)          // coarse grid intervals (= cubic cells)
#define NCTOT  (NC + 3)           // coarse entries: x = (idx-1)/NC
#define RSH    9                  // log2(NFINE/NC) = fine points per cell (512)
#define ZSH    13                 // log2(z-bucket count)
#define ZB     (1 << ZSH)         // z buckets -> 16 KB uint16 map (L1-resident)
#define MONO   1e-3f

__device__ float g_w2t[H * H];    // g_w2t[i*64+j] = exp(pw2[j][i])  (transposed)
__device__ float g_w1[H], g_b1[H], g_b2[H], g_w3[H], g_b3s;
__device__ float g_Ac[NCTOT];     // raw A at coarse grid (+/-1 pad): 8 KB
// per-cell record, 32 B (one L2 sector): [2c]={a,b,c,d} u-scaled; [2c+1]={-1/b, TS[c+1],0,0}
__device__ float4 g_CELL[NC * 2];
__device__ float  g_TS[NC + 1];   // cell-start T values: 8 KB (advance fallback)
__device__ unsigned short g_map[ZB]; // z-bucket -> max cell c with TS[c] <= k/ZB

__device__ __forceinline__ float sigmoidf(float x) {
    return 1.0f / (1.0f + expf(-x));
}

// ---------------------------------------------------------------------------
// Kernel 0: one-shot weight prep -- exponentiate positivity-constrained
// weights, transpose w2 into global.
// ---------------------------------------------------------------------------
__global__ void prep_kernel(const float* __restrict__ pw1, const float* __restrict__ b1,
                            const float* __restrict__ pw2, const float* __restrict__ b2,
                            const float* __restrict__ pw3, const float* __restrict__ b3) {
    int e = blockIdx.x * blockDim.x + threadIdx.x;
    if (e < H * H) {
        int j = e >> 6, i = e & 63;
        g_w2t[i * H + j] = expf(pw2[e]);
    }
    if (e < H) {
        g_w1[e] = expf(pw1[e]);
        g_b1[e] = b1[e];
        g_b2[e] = b2[e];
        g_w3[e] = expf(pw3[e]);
    }
    if (e == 0) g_b3s = b3[0];
}

// ---------------------------------------------------------------------------
// Kernel 1: exact network eval A(x) on the coarse grid, ONE WARP PER POINT.
// ---------------------------------------------------------------------------
__global__ void coarse_kernel() {
    int gwarp = (blockIdx.x * blockDim.x + threadIdx.x) >> 5;
    int lane  = threadIdx.x & 31;
    if (gwarp >= NCTOT) return;
    float x = (float)(gwarp - 1) * (1.0f / (float)NC);

    float h1a = sigmoidf(fmaf(__ldg(&g_w1[lane]),      x, __ldg(&g_b1[lane])));
    float h1b = sigmoidf(fmaf(__ldg(&g_w1[lane + 32]), x, __ldg(&g_b1[lane + 32])));

    float acc0 = __ldg(&g_b2[2 * lane]);
    float acc1 = __ldg(&g_b2[2 * lane + 1]);
#pragma unroll
    for (int i = 0; i < 32; i++) {
        float  hv = __shfl_sync(0xffffffffu, h1a, i);
        float2 w  = __ldg(reinterpret_cast<const float2*>(&g_w2t[i * H + 2 * lane]));
        acc0 = fmaf(w.x, hv, acc0);
        acc1 = fmaf(w.y, hv, acc1);
    }
#pragma unroll
    for (int i = 0; i < 32; i++) {
        float  hv = __shfl_sync(0xffffffffu, h1b, i);
        float2 w  = __ldg(reinterpret_cast<const float2*>(&g_w2t[(i + 32) * H + 2 * lane]));
        acc0 = fmaf(w.x, hv, acc0);
        acc1 = fmaf(w.y, hv, acc1);
    }
    float part = fmaf(sigmoidf(acc0), __ldg(&g_w3[2 * lane]),
                      sigmoidf(acc1) * __ldg(&g_w3[2 * lane + 1]));
#pragma unroll
    for (int o = 16; o; o >>= 1) part += __shfl_xor_sync(0xffffffffu, part, o);

    if (lane == 0) g_Ac[gwarp] = sigmoidf(part + g_b3s) + MONO * x;
}

// ---------------------------------------------------------------------------
// Kernel 2: per-cell records + z-bucket map. u-units (t = u/512; pow2
// divisions exact). TS[c+1] stored with bits identical to cell c+1's 'a'
// (same expression, same inputs). ceil-based runs tile [0, ZB) exactly
// (pow2 scale => exact arithmetic; T monotone in fp32 since A gains
// >= MONO/NC ~ 4.9e-7 per cell >> fp32 eps).
// ---------------------------------------------------------------------------
__global__ void coeff_kernel() {
    int ci = blockIdx.x * blockDim.x + threadIdx.x;
    if (ci >= NC) return;
    const float a0      = g_Ac[1];
    const float a1      = g_Ac[1 + NC];
    const float inv_den = 1.0f / (a1 - a0);
    float P0 = g_Ac[ci];
    float P1 = g_Ac[ci + 1];
    float P2 = g_Ac[ci + 2];
    float P3 = g_Ac[ci + 3];
    float c1 = 0.5f * (P2 - P0);
    float c2 = P0 - 2.5f * P1 + 2.0f * P2 - 0.5f * P3;
    float c3 = 1.5f * (P1 - P2) + 0.5f * (P3 - P0);
    float a  = (P1 - a0) * inv_den;
    float bu = (c1 * inv_den) * (1.0f / 512.0f);
    float cu = (c2 * inv_den) * (1.0f / 262144.0f);
    float du = (c3 * inv_den) * (1.0f / 134217728.0f);
    float tnext = (ci == NC - 1) ? 1.0f : (P2 - a0) * inv_den;

    g_CELL[2 * ci]     = make_float4(a, bu, cu, du);
    g_CELL[2 * ci + 1] = make_float4(-1.0f / bu, tnext, 0.0f, 0.0f);
    g_TS[ci] = a;                           // cell 0 -> exactly 0.0f
    if (ci == NC - 1) g_TS[NC] = 1.0f;

    int k0 = (int)ceilf(a     * (float)ZB); // exact: pow2 scale
    int k1 = (int)ceilf(tnext * (float)ZB);
    if (k0 < 0) k0 = 0;
    if (k1 > ZB) k1 = ZB;
    for (int k = k0; k < k1; k++) g_map[k] = (unsigned short)ci;
}

// T at fine offset u within a cell (u-scaled coeffs): 3 FMA, bit-identical
// expression everywhere it is used.
__device__ __forceinline__ float horner_u(float4 cf, float u) {
    return fmaf(u, fmaf(u, fmaf(u, cf.w, cf.z), cf.y), cf.x);
}

// ---------------------------------------------------------------------------
// Kernel 3: 4 targets/thread, phase-batched for 4-way ILP (the kernel is
// latency-bound on short L1 chains, so explicit MLP wins here). Per z:
// u16 map load -> one 32B cell record (two float4s, SAME sector) -> rare
// advance (expected 0.125 iters) -> division-free chord (3 iters, 4 FMA
// each) -> BRANCH-FREE predicated +/-2 index corrections (no BSSY/BSYNC,
// no divergence). Semantics: j = max{j : T(j) <= z} on the fine grid
// (up to fp32-noise-level +/-1 at cell seams, ~1e-6 output effect);
// out = (j + 0.5) * 2^-20.
// ---------------------------------------------------------------------------
__device__ __forceinline__ float invert_one(float zi) {
    int k = (int)(zi * (float)ZB);               // exact floor: pow2 scale
    k = min(max(k, 0), ZB - 1);
    int ci = (int)__ldg(&g_map[k]);              // TS[ci] <= k/ZB <= zi
    float4 ca = __ldg(&g_CELL[2 * ci]);
    float4 cb = __ldg(&g_CELL[2 * ci + 1]);
    if (cb.y <= zi) {                            // rare: advance to later cell
        ci++;
        while (__ldg(&g_TS[ci + 1]) <= zi) ci++; // TS[NC]=1 > z ends the loop
        ca = __ldg(&g_CELL[2 * ci]);
        cb = __ldg(&g_CELL[2 * ci + 1]);
    }
    float nrb = cb.x;                            // -1/b
    float u = (ca.x - zi) * nrb;                 // linear seed = (zi - a)/b
    u = fminf(fmaxf(u, 0.0f), 512.0f);
#pragma unroll
    for (int it = 0; it < 3; it++)
        u = fmaf(horner_u(ca, u) - zi, nrb, u);  // u -= (T(u) - z)/b
    u = fminf(fmaxf(u, 0.0f), 511.0f);           // NaN-safe
    int ui = (int)u;
    // predicated corrections (+/-2 window; T(0)=a <= z keeps ui >= 0)
    ui -= (horner_u(ca, (float)ui) > zi);
    ui -= (horner_u(ca, (float)ui) > zi);
    ui += (horner_u(ca, (float)(ui + 1)) <= zi);
    ui += (horner_u(ca, (float)(ui + 1)) <= zi);
    ui = min(ui, 512);
    int j = (ci << RSH) + ui;
    return (float)(2 * j + 1) * 0x1p-21f;        // (j + 0.5) * 2^-20, exact
}

__global__ void search_kernel(const float* __restrict__ z, float* __restrict__ out, int n) {
    int i = (blockIdx.x * blockDim.x + threadIdx.x) * 4;
    if (i + 3 < n) {
        float4 zv = *reinterpret_cast<const float4*>(z + i);
        float zr[4] = {zv.x, zv.y, zv.z, zv.w};
        int   k[4], ci[4];
        float4 ca[4], cb[4];
#pragma unroll
        for (int m = 0; m < 4; m++) {
            k[m] = (int)(zr[m] * (float)ZB);
            k[m] = min(max(k[m], 0), ZB - 1);
        }
#pragma unroll
        for (int m = 0; m < 4; m++) ci[m] = (int)__ldg(&g_map[k[m]]);  // 4 indep loads
#pragma unroll
        for (int m = 0; m < 4; m++) {
            ca[m] = __ldg(&g_CELL[2 * ci[m]]);       // 4 indep 32B records
            cb[m] = __ldg(&g_CELL[2 * ci[m] + 1]);   // same sector as ca[m]
        }
#pragma unroll
        for (int m = 0; m < 4; m++) {
            if (cb[m].y <= zr[m]) {                  // rare advance path
                ci[m]++;
                while (__ldg(&g_TS[ci[m] + 1]) <= zr[m]) ci[m]++;
                ca[m] = __ldg(&g_CELL[2 * ci[m]]);
                cb[m] = __ldg(&g_CELL[2 * ci[m] + 1]);
            }
        }
        float ov[4];
#pragma unroll
        for (int m = 0; m < 4; m++) {
            float nrb = cb[m].x;
            float u = (ca[m].x - zr[m]) * nrb;
            u = fminf(fmaxf(u, 0.0f), 512.0f);
#pragma unroll
            for (int it = 0; it < 3; it++)
                u = fmaf(horner_u(ca[m], u) - zr[m], nrb, u);
            u = fminf(fmaxf(u, 0.0f), 511.0f);
            int ui = (int)u;
            ui -= (horner_u(ca[m], (float)ui) > zr[m]);
            ui -= (horner_u(ca[m], (float)ui) > zr[m]);
            ui += (horner_u(ca[m], (float)(ui + 1)) <= zr[m]);
            ui += (horner_u(ca[m], (float)(ui + 1)) <= zr[m]);
            ui = min(ui, 512);
            int j = (ci[m] << RSH) + ui;
            ov[m] = (float)(2 * j + 1) * 0x1p-21f;
        }
        *reinterpret_cast<float4*>(out + i) = make_float4(ov[0], ov[1], ov[2], ov[3]);
    } else {
        for (; i < n; i++) out[i] = invert_one(z[i]);
    }
}

// ---------------------------------------------------------------------------
extern "C" void kernel_launch(void* const* d_in, const int* in_sizes, int n_in,
                              void* d_out, int out_size) {
    const float* z   = (const float*)d_in[0];
    const float* pw1 = (const float*)d_in[1];
    const float* b1  = (const float*)d_in[2];
    const float* pw2 = (const float*)d_in[3];
    const float* b2  = (const float*)d_in[4];
    const float* pw3 = (const float*)d_in[5];
    const float* b3  = (const float*)d_in[6];
    float* out = (float*)d_out;
    int n = in_sizes[0];

    prep_kernel<<<(H * H + 255) / 256, 256>>>(pw1, b1, pw2, b2, pw3, b3);
    coarse_kernel<<<(NCTOT * 32 + 255) / 256, 256>>>();
    coeff_kernel<<<(NC + 255) / 256, 256>>>();
    int nq = (n + 3) / 4;
    search_kernel<<<(nq + 255) / 256, 256>>>(z, out, n);
}

// round 15
// speedup vs baseline: 1.0779x; 1.0779x over previous
#include <cuda_runtime.h>
#include <math.h>

#define H      64
#define NFINE  (1 << 20)          // fine grid intervals over [0,1]
#define NC     (1 << 11)          // coarse grid intervals (= cubic cells)
#define NCTOT  (NC + 3)           // coarse entries: x = (idx-1)/NC
#define RSH    9                  // log2(NFINE/NC) = fine points per cell (512)
#define ZSH    13                 // log2(z-bucket count)
#define ZB     (1 << ZSH)         // z buckets -> 16 KB uint16 map (L1-resident)
#define MONO   1e-3f

__device__ float g_w2t[H * H];    // g_w2t[i*64+j] = exp(pw2[j][i])  (transposed)
__device__ float g_w1[H], g_b1[H], g_b2[H], g_w3[H], g_b3s;
__device__ float g_Ac[NCTOT];     // raw A at coarse grid (+/-1 pad): 8 KB
// per-cell record, 32 B (one L2 sector): [2c]={a,b,c,d} u-scaled; [2c+1]={-1/b, TS[c+1],0,0}
__device__ float4 g_CELL[NC * 2];
__device__ float  g_TS[NC + 1];   // cell-start T values: 8 KB (advance fallback)
__device__ unsigned short g_map[ZB]; // z-bucket -> max cell c with TS[c] <= k/ZB

__device__ __forceinline__ float sigmoidf(float x) {
    return 1.0f / (1.0f + expf(-x));
}

// ---------------------------------------------------------------------------
// Kernel 0: one-shot weight prep -- exponentiate positivity-constrained
// weights, transpose w2 into global.
// ---------------------------------------------------------------------------
__global__ void prep_kernel(const float* __restrict__ pw1, const float* __restrict__ b1,
                            const float* __restrict__ pw2, const float* __restrict__ b2,
                            const float* __restrict__ pw3, const float* __restrict__ b3) {
    int e = blockIdx.x * blockDim.x + threadIdx.x;
    if (e < H * H) {
        int j = e >> 6, i = e & 63;
        g_w2t[i * H + j] = expf(pw2[e]);
    }
    if (e < H) {
        g_w1[e] = expf(pw1[e]);
        g_b1[e] = b1[e];
        g_b2[e] = b2[e];
        g_w3[e] = expf(pw3[e]);
    }
    if (e == 0) g_b3s = b3[0];
}

// ---------------------------------------------------------------------------
// Kernel 1: exact network eval A(x) on the coarse grid, ONE WARP PER POINT.
// ---------------------------------------------------------------------------
__global__ void coarse_kernel() {
    int gwarp = (blockIdx.x * blockDim.x + threadIdx.x) >> 5;
    int lane  = threadIdx.x & 31;
    if (gwarp >= NCTOT) return;
    float x = (float)(gwarp - 1) * (1.0f / (float)NC);

    float h1a = sigmoidf(fmaf(__ldg(&g_w1[lane]),      x, __ldg(&g_b1[lane])));
    float h1b = sigmoidf(fmaf(__ldg(&g_w1[lane + 32]), x, __ldg(&g_b1[lane + 32])));

    float acc0 = __ldg(&g_b2[2 * lane]);
    float acc1 = __ldg(&g_b2[2 * lane + 1]);
#pragma unroll
    for (int i = 0; i < 32; i++) {
        float  hv = __shfl_sync(0xffffffffu, h1a, i);
        float2 w  = __ldg(reinterpret_cast<const float2*>(&g_w2t[i * H + 2 * lane]));
        acc0 = fmaf(w.x, hv, acc0);
        acc1 = fmaf(w.y, hv, acc1);
    }
#pragma unroll
    for (int i = 0; i < 32; i++) {
        float  hv = __shfl_sync(0xffffffffu, h1b, i);
        float2 w  = __ldg(reinterpret_cast<const float2*>(&g_w2t[(i + 32) * H + 2 * lane]));
        acc0 = fmaf(w.x, hv, acc0);
        acc1 = fmaf(w.y, hv, acc1);
    }
    float part = fmaf(sigmoidf(acc0), __ldg(&g_w3[2 * lane]),
                      sigmoidf(acc1) * __ldg(&g_w3[2 * lane + 1]));
#pragma unroll
    for (int o = 16; o; o >>= 1) part += __shfl_xor_sync(0xffffffffu, part, o);

    if (lane == 0) g_Ac[gwarp] = sigmoidf(part + g_b3s) + MONO * x;
}

// ---------------------------------------------------------------------------
// Kernel 2: per-cell records + z-bucket map. u-units (t = u/512; pow2
// divisions exact). TS[c+1] stored with bits identical to cell c+1's 'a'
// (same expression, same inputs). ceil-based runs tile [0, ZB) exactly
// (pow2 scale => exact arithmetic; T monotone in fp32 since A gains
// >= MONO/NC ~ 4.9e-7 per cell >> fp32 eps).
// ---------------------------------------------------------------------------
__global__ void coeff_kernel() {
    int ci = blockIdx.x * blockDim.x + threadIdx.x;
    if (ci >= NC) return;
    const float a0      = g_Ac[1];
    const float a1      = g_Ac[1 + NC];
    const float inv_den = 1.0f / (a1 - a0);
    float P0 = g_Ac[ci];
    float P1 = g_Ac[ci + 1];
    float P2 = g_Ac[ci + 2];
    float P3 = g_Ac[ci + 3];
    float c1 = 0.5f * (P2 - P0);
    float c2 = P0 - 2.5f * P1 + 2.0f * P2 - 0.5f * P3;
    float c3 = 1.5f * (P1 - P2) + 0.5f * (P3 - P0);
    float a  = (P1 - a0) * inv_den;
    float bu = (c1 * inv_den) * (1.0f / 512.0f);
    float cu = (c2 * inv_den) * (1.0f / 262144.0f);
    float du = (c3 * inv_den) * (1.0f / 134217728.0f);
    float tnext = (ci == NC - 1) ? 1.0f : (P2 - a0) * inv_den;

    g_CELL[2 * ci]     = make_float4(a, bu, cu, du);
    g_CELL[2 * ci + 1] = make_float4(-1.0f / bu, tnext, 0.0f, 0.0f);
    g_TS[ci] = a;                           // cell 0 -> exactly 0.0f
    if (ci == NC - 1) g_TS[NC] = 1.0f;

    int k0 = (int)ceilf(a     * (float)ZB); // exact: pow2 scale
    int k1 = (int)ceilf(tnext * (float)ZB);
    if (k0 < 0) k0 = 0;
    if (k1 > ZB) k1 = ZB;
    for (int k = k0; k < k1; k++) g_map[k] = (unsigned short)ci;
}

// T at fine offset u within a cell (u-scaled coeffs): 3 FMA, bit-identical
// expression everywhere it is used.
__device__ __forceinline__ float horner_u(float4 cf, float u) {
    return fmaf(u, fmaf(u, fmaf(u, cf.w, cf.z), cf.y), cf.x);
}

// ---------------------------------------------------------------------------
// Kernel 3: per-target inversion -- SEQUENTIAL low-register form (the
// thrice-proven winner: R5/R6/R14 all showed explicit batching loses to the
// HW scoreboard at lower occupancy), 2 targets/thread, with R14's two good
// ingredients kept: (a) one 32B single-sector cell record per z, (b)
// BRANCH-FREE predicated +/-2 index corrections (no BSSY/BSYNC in the
// common path). Per z: u16 map load -> 32B record -> rare advance
// (expected ~12.5% one extra compare) -> division-free 3-iter chord ->
// predicated corrections. Semantics: j = max{j : T(j) <= z} on the fine
// grid (up to fp32-noise +/-1 at seams, ~1e-6 output effect);
// out = (j + 0.5) * 2^-20.
// ---------------------------------------------------------------------------
__device__ __forceinline__ float invert_one(float zi) {
    int k = (int)(zi * (float)ZB);               // exact floor: pow2 scale
    k = min(max(k, 0), ZB - 1);
    int ci = (int)__ldg(&g_map[k]);              // TS[ci] <= k/ZB <= zi
    float4 ca = __ldg(&g_CELL[2 * ci]);
    float4 cb = __ldg(&g_CELL[2 * ci + 1]);      // same 32B sector as ca
    if (cb.y <= zi) {                            // rare: advance to later cell
        ci++;
        while (__ldg(&g_TS[ci + 1]) <= zi) ci++; // TS[NC]=1 > z ends the loop
        ca = __ldg(&g_CELL[2 * ci]);
        cb = __ldg(&g_CELL[2 * ci + 1]);
    }
    float nrb = cb.x;                            // -1/b
    float u = (ca.x - zi) * nrb;                 // linear seed = (zi - a)/b
    u = fminf(fmaxf(u, 0.0f), 512.0f);
#pragma unroll
    for (int it = 0; it < 3; it++)
        u = fmaf(horner_u(ca, u) - zi, nrb, u);  // u -= (T(u) - z)/b
    u = fminf(fmaxf(u, 0.0f), 511.0f);           // NaN-safe
    int ui = (int)u;
    // predicated corrections (+/-2 window; T(0)=a <= z keeps ui >= 0)
    ui -= (horner_u(ca, (float)ui) > zi);
    ui -= (horner_u(ca, (float)ui) > zi);
    ui += (horner_u(ca, (float)(ui + 1)) <= zi);
    ui += (horner_u(ca, (float)(ui + 1)) <= zi);
    ui = min(ui, 512);
    int j = (ci << RSH) + ui;
    return (float)(2 * j + 1) * 0x1p-21f;        // (j + 0.5) * 2^-20, exact
}

__global__ void search_kernel(const float* __restrict__ z, float* __restrict__ out, int n) {
    int i = (blockIdx.x * blockDim.x + threadIdx.x) * 2;
    if (i + 1 < n) {
        float2 zv = *reinterpret_cast<const float2*>(z + i);
        float2 ov;
        ov.x = invert_one(zv.x);
        ov.y = invert_one(zv.y);
        *reinterpret_cast<float2*>(out + i) = ov;
    } else if (i < n) {
        out[i] = invert_one(z[i]);
    }
}

// ---------------------------------------------------------------------------
extern "C" void kernel_launch(void* const* d_in, const int* in_sizes, int n_in,
                              void* d_out, int out_size) {
    const float* z   = (const float*)d_in[0];
    const float* pw1 = (const float*)d_in[1];
    const float* b1  = (const float*)d_in[2];
    const float* pw2 = (const float*)d_in[3];
    const float* b2  = (const float*)d_in[4];
    const float* pw3 = (const float*)d_in[5];
    const float* b3  = (const float*)d_in[6];
    float* out = (float*)d_out;
    int n = in_sizes[0];

    prep_kernel<<<(H * H + 255) / 256, 256>>>(pw1, b1, pw2, b2, pw3, b3);
    coarse_kernel<<<(NCTOT * 32 + 255) / 256, 256>>>();
    coeff_kernel<<<(NC + 255) / 256, 256>>>();
    int nq = (n + 1) / 2;
    search_kernel<<<(nq + 255) / 256, 256>>>(z, out, n);
}